// round 1
// baseline (speedup 1.0000x reference)
#include <cuda_runtime.h>

#define BB 4
#define TT 2048
#define FF 1024
#define HH 16
#define DH 64
#define SCALE 0.03125f   // 1024^-0.5

// Scratch (device globals: allocation-free, harness-legal)
__device__ float g_qkv[(size_t)3 * BB * HH * TT * DH];   // [k][b][h][t][d]
__device__ float g_ao[(size_t)BB * HH * TT * DH];        // [b][h][t][d]

// ---------------------------------------------------------------------------
// K1: QKV projection.  C[m][n] = sum_f x[m][f] * w_qkv[o(n)][f]
// m = b*T + t.  Our n ordering: n = k*1024 + h*64 + d, and the reference's
// channel layout is o = d*48 + k*16 + h.  Each 64-wide N tile = one (k,h).
// ---------------------------------------------------------------------------
__global__ __launch_bounds__(256) void qkv_gemm_kernel(const float* __restrict__ x,
                                                       const float* __restrict__ w) {
    __shared__ float As[16][68];   // As[kk][m]  (transposed)
    __shared__ float Bs[16][68];   // Bs[kk][n]  (transposed)
    const int m0 = blockIdx.y * 64;
    const int nt = blockIdx.x;              // 48 tiles
    const int kq = nt >> 4, hq = nt & 15;
    const int t  = threadIdx.x;
    const int tx = t & 15, ty = t >> 4;
    const int lrow = t >> 2, lc4 = t & 3;

    const float* __restrict__ xp = x + (size_t)(m0 + lrow) * FF + lc4 * 4;
    const int orow = lrow * 48 + kq * 16 + hq;            // permuted weight row
    const float* __restrict__ wp = w + (size_t)orow * FF + lc4 * 4;

    float acc[4][4];
    #pragma unroll
    for (int i = 0; i < 4; i++)
        #pragma unroll
        for (int j = 0; j < 4; j++) acc[i][j] = 0.f;

    for (int k0 = 0; k0 < FF; k0 += 16) {
        float4 av = *(const float4*)(xp + k0);
        float4 bv = *(const float4*)(wp + k0);
        __syncthreads();
        As[lc4*4+0][lrow] = av.x; As[lc4*4+1][lrow] = av.y;
        As[lc4*4+2][lrow] = av.z; As[lc4*4+3][lrow] = av.w;
        Bs[lc4*4+0][lrow] = bv.x; Bs[lc4*4+1][lrow] = bv.y;
        Bs[lc4*4+2][lrow] = bv.z; Bs[lc4*4+3][lrow] = bv.w;
        __syncthreads();
        #pragma unroll
        for (int kk = 0; kk < 16; kk++) {
            float4 a = *(const float4*)&As[kk][ty * 4];
            float4 b = *(const float4*)&Bs[kk][tx * 4];
            float aa[4] = {a.x, a.y, a.z, a.w};
            float bb[4] = {b.x, b.y, b.z, b.w};
            #pragma unroll
            for (int i = 0; i < 4; i++)
                #pragma unroll
                for (int j = 0; j < 4; j++) acc[i][j] += aa[i] * bb[j];
        }
    }
    #pragma unroll
    for (int i = 0; i < 4; i++) {
        int m = m0 + ty * 4 + i;
        int b = m >> 11, tseq = m & 2047;
        size_t base = ((((size_t)kq * BB + b) * HH + hq) * TT + tseq) * DH + tx * 4;
        *(float4*)&g_qkv[base] = make_float4(acc[i][0], acc[i][1], acc[i][2], acc[i][3]);
    }
}

// ---------------------------------------------------------------------------
// K2: flash attention. grid = (T/64, B*H). 256 threads, 4x4 per thread.
// Qs/Ks/Ps transposed in smem (pad 68), Vs natural (row 64).
// ---------------------------------------------------------------------------
#define QL 68
#define ATTN_SMEM (3 * 64 * QL * 4 + 64 * DH * 4)   // 68608 bytes

__global__ __launch_bounds__(256) void attn_kernel() {
    extern __shared__ float sm[];
    float* Qs = sm;                 // Qs[d][r], scaled by SCALE
    float* Ks = Qs + 64 * QL;       // Ks[d][c]
    float* Ps = Ks + 64 * QL;       // Ps[c][r]
    float* Vs = Ps + 64 * QL;       // Vs[j][d]

    const int bh = blockIdx.y;
    const int i0 = blockIdx.x * 64;
    const int t  = threadIdx.x;
    const int tx = t & 15, ty = t >> 4;

    const float* Qg = g_qkv + ((size_t)bh * TT + i0) * DH;
    const float* Kg = g_qkv + (size_t)BB * HH * TT * DH + (size_t)bh * TT * DH;
    const float* Vg = g_qkv + (size_t)2 * BB * HH * TT * DH + (size_t)bh * TT * DH;

    // Load Q tile (transposed, pre-scaled)
    #pragma unroll
    for (int rep = 0; rep < 4; rep++) {
        int ii = rep * 256 + t;
        int row = ii >> 4, c4 = ii & 15;
        float4 v = *(const float4*)(Qg + (size_t)row * DH + c4 * 4);
        Qs[(c4*4+0)*QL + row] = v.x * SCALE;
        Qs[(c4*4+1)*QL + row] = v.y * SCALE;
        Qs[(c4*4+2)*QL + row] = v.z * SCALE;
        Qs[(c4*4+3)*QL + row] = v.w * SCALE;
    }

    float mi[4], li[4], o[4][4];
    #pragma unroll
    for (int i = 0; i < 4; i++) {
        mi[i] = -1e30f; li[i] = 0.f;
        #pragma unroll
        for (int j = 0; j < 4; j++) o[i][j] = 0.f;
    }

    for (int j0 = 0; j0 < TT; j0 += 64) {
        __syncthreads();   // previous PV done before overwriting K/V
        #pragma unroll
        for (int rep = 0; rep < 4; rep++) {
            int ii = rep * 256 + t;
            int row = ii >> 4, c4 = ii & 15;
            float4 kv = *(const float4*)(Kg + (size_t)(j0 + row) * DH + c4 * 4);
            Ks[(c4*4+0)*QL + row] = kv.x; Ks[(c4*4+1)*QL + row] = kv.y;
            Ks[(c4*4+2)*QL + row] = kv.z; Ks[(c4*4+3)*QL + row] = kv.w;
            float4 vv = *(const float4*)(Vg + (size_t)(j0 + row) * DH + c4 * 4);
            *(float4*)&Vs[row * DH + c4 * 4] = vv;
        }
        __syncthreads();

        // S = (Q*SCALE) K^T  (64x64, 4x4 per thread)
        float s[4][4];
        #pragma unroll
        for (int i = 0; i < 4; i++)
            #pragma unroll
            for (int j = 0; j < 4; j++) s[i][j] = 0.f;
        #pragma unroll 16
        for (int d = 0; d < DH; d++) {
            float4 a = *(const float4*)&Qs[d * QL + ty * 4];
            float4 b = *(const float4*)&Ks[d * QL + tx * 4];
            float aa[4] = {a.x, a.y, a.z, a.w};
            float bb[4] = {b.x, b.y, b.z, b.w};
            #pragma unroll
            for (int i = 0; i < 4; i++)
                #pragma unroll
                for (int j = 0; j < 4; j++) s[i][j] += aa[i] * bb[j];
        }

        // Online softmax. Rows are shared by the 16 tx-lanes of a half-warp.
        float mloc[4];
        #pragma unroll
        for (int i = 0; i < 4; i++)
            mloc[i] = fmaxf(fmaxf(s[i][0], s[i][1]), fmaxf(s[i][2], s[i][3]));
        #pragma unroll
        for (int off = 8; off >= 1; off >>= 1)
            #pragma unroll
            for (int i = 0; i < 4; i++)
                mloc[i] = fmaxf(mloc[i], __shfl_xor_sync(0xffffffffu, mloc[i], off));

        float alpha[4], lloc[4];
        #pragma unroll
        for (int i = 0; i < 4; i++) {
            float mn = fmaxf(mi[i], mloc[i]);
            alpha[i] = __expf(mi[i] - mn);
            mi[i] = mn;
            #pragma unroll
            for (int j = 0; j < 4; j++) s[i][j] = __expf(s[i][j] - mn);
            lloc[i] = s[i][0] + s[i][1] + s[i][2] + s[i][3];
        }
        #pragma unroll
        for (int off = 8; off >= 1; off >>= 1)
            #pragma unroll
            for (int i = 0; i < 4; i++)
                lloc[i] += __shfl_xor_sync(0xffffffffu, lloc[i], off);
        #pragma unroll
        for (int i = 0; i < 4; i++) {
            li[i] = li[i] * alpha[i] + lloc[i];
            #pragma unroll
            for (int j = 0; j < 4; j++) o[i][j] *= alpha[i];
        }

        // P to smem (transposed), then O += P V
        #pragma unroll
        for (int i = 0; i < 4; i++)
            #pragma unroll
            for (int j = 0; j < 4; j++)
                Ps[(tx * 4 + j) * QL + ty * 4 + i] = s[i][j];
        __syncthreads();
        #pragma unroll 16
        for (int jj = 0; jj < 64; jj++) {
            float4 a = *(const float4*)&Ps[jj * QL + ty * 4];
            float4 b = *(const float4*)&Vs[jj * DH + tx * 4];
            float aa[4] = {a.x, a.y, a.z, a.w};
            float bb[4] = {b.x, b.y, b.z, b.w};
            #pragma unroll
            for (int i = 0; i < 4; i++)
                #pragma unroll
                for (int j = 0; j < 4; j++) o[i][j] += aa[i] * bb[j];
        }
    }

    #pragma unroll
    for (int i = 0; i < 4; i++) {
        float inv = 1.f / li[i];
        size_t base = ((size_t)bh * TT + i0 + ty * 4 + i) * DH + tx * 4;
        *(float4*)&g_ao[base] =
            make_float4(o[i][0] * inv, o[i][1] * inv, o[i][2] * inv, o[i][3] * inv);
    }
}

// ---------------------------------------------------------------------------
// K3: output projection + bias.  A[m][kk] = g_ao[b][kk>>6][t][kk&63]
// ---------------------------------------------------------------------------
__global__ __launch_bounds__(256) void out_gemm_kernel(const float* __restrict__ w,
                                                       const float* __restrict__ bias,
                                                       float* __restrict__ y) {
    __shared__ float As[16][68];
    __shared__ float Bs[16][68];
    const int m0 = blockIdx.y * 64;
    const int n0 = blockIdx.x * 64;
    const int t  = threadIdx.x;
    const int tx = t & 15, ty = t >> 4;
    const int lrow = t >> 2, lc4 = t & 3;

    const int m = m0 + lrow;
    const int b = m >> 11, tseq = m & 2047;
    const float* __restrict__ wp = w + (size_t)(n0 + lrow) * FF + lc4 * 4;

    float acc[4][4];
    #pragma unroll
    for (int i = 0; i < 4; i++)
        #pragma unroll
        for (int j = 0; j < 4; j++) acc[i][j] = 0.f;

    for (int k0 = 0; k0 < FF; k0 += 16) {
        int kk = k0 + lc4 * 4;
        int h = kk >> 6, dd = kk & 63;
        float4 av = *(const float4*)&g_ao[(((size_t)b * HH + h) * TT + tseq) * DH + dd];
        float4 bv = *(const float4*)(wp + k0);
        __syncthreads();
        As[lc4*4+0][lrow] = av.x; As[lc4*4+1][lrow] = av.y;
        As[lc4*4+2][lrow] = av.z; As[lc4*4+3][lrow] = av.w;
        Bs[lc4*4+0][lrow] = bv.x; Bs[lc4*4+1][lrow] = bv.y;
        Bs[lc4*4+2][lrow] = bv.z; Bs[lc4*4+3][lrow] = bv.w;
        __syncthreads();
        #pragma unroll
        for (int kkk = 0; kkk < 16; kkk++) {
            float4 a = *(const float4*)&As[kkk][ty * 4];
            float4 bq = *(const float4*)&Bs[kkk][tx * 4];
            float aa[4] = {a.x, a.y, a.z, a.w};
            float bb[4] = {bq.x, bq.y, bq.z, bq.w};
            #pragma unroll
            for (int i = 0; i < 4; i++)
                #pragma unroll
                for (int j = 0; j < 4; j++) acc[i][j] += aa[i] * bb[j];
        }
    }

    float4 bv = *(const float4*)&bias[n0 + tx * 4];
    float bb[4] = {bv.x, bv.y, bv.z, bv.w};
    #pragma unroll
    for (int i = 0; i < 4; i++) {
        int mm = m0 + ty * 4 + i;
        *(float4*)&y[(size_t)mm * FF + n0 + tx * 4] =
            make_float4(acc[i][0] + bb[0], acc[i][1] + bb[1],
                        acc[i][2] + bb[2], acc[i][3] + bb[3]);
    }
}

// ---------------------------------------------------------------------------
extern "C" void kernel_launch(void* const* d_in, const int* in_sizes, int n_in,
                              void* d_out, int out_size) {
    const float* x    = (const float*)d_in[0];
    const float* wqkv = (const float*)d_in[1];
    const float* wout = (const float*)d_in[2];
    const float* bout = (const float*)d_in[3];
    float* y = (float*)d_out;

    cudaFuncSetAttribute(attn_kernel, cudaFuncAttributeMaxDynamicSharedMemorySize,
                         ATTN_SMEM);

    qkv_gemm_kernel<<<dim3(48, 128), 256>>>(x, wqkv);
    attn_kernel<<<dim3(TT / 64, BB * HH), 256, ATTN_SMEM>>>();
    out_gemm_kernel<<<dim3(16, 128), 256>>>(wout, bout, y);
}

// round 3
// speedup vs baseline: 3.5448x; 3.5448x over previous
#include <cuda_runtime.h>
#include <cstdint>

#define BB 4
#define TT 2048
#define FF 1024
#define HH 16
#define DH 64
#define SCALE 0.03125f   // 1024^-0.5

// Scratch (device globals: allocation-free, harness-legal)
__device__ float g_qkv[(size_t)3 * BB * HH * TT * DH];   // [k][b][h][t][d]
__device__ float g_ao[(size_t)BB * HH * TT * DH];        // [b][h][t][d]

__device__ __forceinline__ unsigned f2t(float f) {
    unsigned r; asm("cvt.rna.tf32.f32 %0, %1;" : "=r"(r) : "f"(f)); return r;
}
__device__ __forceinline__ void mma8(float c[4], const unsigned a[4],
                                     unsigned b0, unsigned b1) {
    asm volatile(
        "mma.sync.aligned.m16n8k8.row.col.f32.tf32.tf32.f32 "
        "{%0,%1,%2,%3},{%4,%5,%6,%7},{%8,%9},{%0,%1,%2,%3};"
        : "+f"(c[0]), "+f"(c[1]), "+f"(c[2]), "+f"(c[3])
        : "r"(a[0]), "r"(a[1]), "r"(a[2]), "r"(a[3]), "r"(b0), "r"(b1));
}

// ---------------------------------------------------------------------------
// Tensor-core GEMM: C[m][n] = sum_k A[m][k] * B[n][k]  (+permutation gathers)
// MODE 0: A=x, B=w_qkv (rows permuted o=d*48+kq*16+hq), C -> g_qkv[k][b][h][t][d]
// MODE 1: A=g_ao gathered (kk = h*64+d), B=w_out, C -> y + bias
// Block 128x128, ktile 32, 8 warps (4m x 2n), warp tile 32x64, double buffer.
// ---------------------------------------------------------------------------
#define GLD 36
#define GEMM_SMEM (2 * 2 * 128 * GLD * 4)   // 73728 bytes

template<int MODE>
__global__ __launch_bounds__(256) void gemm_tc(const float* __restrict__ A,
                                               const float* __restrict__ W,
                                               const float* __restrict__ bias,
                                               float* __restrict__ out) {
    extern __shared__ unsigned smg[];
    unsigned* As = smg;                   // [2][128][GLD]
    unsigned* Bs = smg + 2 * 128 * GLD;   // [2][128][GLD]

    const int tid = threadIdx.x;
    const int lane = tid & 31, w = tid >> 5;
    const int g = lane >> 2, tig = lane & 3;
    const int wm = (w & 3) * 32, wn = (w >> 2) * 64;
    const int m0 = blockIdx.y * 128, n0 = blockIdx.x * 128;
    const int lrow = tid >> 3;           // 0..31
    const int kc = (tid & 7) * 4;

    float acc[2][8][4];
    #pragma unroll
    for (int mt = 0; mt < 2; mt++)
        #pragma unroll
        for (int nt = 0; nt < 8; nt++)
            #pragma unroll
            for (int i = 0; i < 4; i++) acc[mt][nt][i] = 0.f;

    float4 ar[4], br[4];

    auto gload = [&](int k0) {
        #pragma unroll
        for (int r = 0; r < 4; r++) {
            int row = lrow + r * 32;
            if (MODE == 0) {
                ar[r] = *(const float4*)(A + (size_t)(m0 + row) * FF + k0 + kc);
            } else {
                int m = m0 + row; int b = m >> 11, t = m & 2047;
                int kk = k0 + kc; int h = kk >> 6, dd = kk & 63;
                ar[r] = *(const float4*)&g_ao[(((size_t)b * HH + h) * TT + t) * DH + dd];
            }
            int n = n0 + row;
            const float* wp;
            if (MODE == 0) {
                int kq = n >> 10, hq = (n >> 6) & 15, d = n & 63;
                wp = W + (size_t)(d * 48 + kq * 16 + hq) * FF + k0 + kc;
            } else {
                wp = W + (size_t)n * FF + k0 + kc;
            }
            br[r] = *(const float4*)wp;
        }
    };

    auto sts = [&](int buf) {
        unsigned* Ab = As + buf * 128 * GLD;
        unsigned* Bb = Bs + buf * 128 * GLD;
        #pragma unroll
        for (int r = 0; r < 4; r++) {
            int row = lrow + r * 32;
            *(uint4*)&Ab[row * GLD + kc] =
                make_uint4(f2t(ar[r].x), f2t(ar[r].y), f2t(ar[r].z), f2t(ar[r].w));
            *(uint4*)&Bb[row * GLD + kc] =
                make_uint4(f2t(br[r].x), f2t(br[r].y), f2t(br[r].z), f2t(br[r].w));
        }
    };

    auto compute = [&](int buf) {
        const unsigned* Ab = As + buf * 128 * GLD;
        const unsigned* Bb = Bs + buf * 128 * GLD;
        #pragma unroll
        for (int kit = 0; kit < 4; kit++) {
            unsigned a[2][4], b[8][2];
            #pragma unroll
            for (int mt = 0; mt < 2; mt++) {
                int mrow = wm + mt * 16 + g;
                a[mt][0] = Ab[mrow * GLD + kit * 8 + tig];
                a[mt][1] = Ab[(mrow + 8) * GLD + kit * 8 + tig];
                a[mt][2] = Ab[mrow * GLD + kit * 8 + tig + 4];
                a[mt][3] = Ab[(mrow + 8) * GLD + kit * 8 + tig + 4];
            }
            #pragma unroll
            for (int nt = 0; nt < 8; nt++) {
                int nrow = wn + nt * 8 + g;
                b[nt][0] = Bb[nrow * GLD + kit * 8 + tig];
                b[nt][1] = Bb[nrow * GLD + kit * 8 + tig + 4];
            }
            #pragma unroll
            for (int mt = 0; mt < 2; mt++)
                #pragma unroll
                for (int nt = 0; nt < 8; nt++)
                    mma8(acc[mt][nt], a[mt], b[nt][0], b[nt][1]);
        }
    };

    gload(0); sts(0); __syncthreads();
    const int NK = FF / 32;
    #pragma unroll 1
    for (int kt = 0; kt < NK; kt++) {
        if (kt + 1 < NK) gload((kt + 1) * 32);
        compute(kt & 1);
        if (kt + 1 < NK) { sts((kt + 1) & 1); __syncthreads(); }
    }

    #pragma unroll
    for (int mt = 0; mt < 2; mt++)
        #pragma unroll
        for (int nt = 0; nt < 8; nt++) {
            int n = n0 + wn + nt * 8 + 2 * tig;
            #pragma unroll
            for (int half = 0; half < 2; half++) {
                int m = m0 + wm + mt * 16 + g + half * 8;
                float c0 = acc[mt][nt][half * 2 + 0];
                float c1 = acc[mt][nt][half * 2 + 1];
                if (MODE == 0) {
                    int b = m >> 11, t = m & 2047;
                    int kq = n >> 10, hq = (n >> 6) & 15, d = n & 63;
                    *(float2*)&g_qkv[((((size_t)kq * BB + b) * HH + hq) * TT + t) * DH + d] =
                        make_float2(c0, c1);
                } else {
                    float2 bv = *(const float2*)&bias[n];
                    *(float2*)&out[(size_t)m * FF + n] =
                        make_float2(c0 + bv.x, c1 + bv.y);
                }
            }
        }
}

// ---------------------------------------------------------------------------
// Flash attention on tensor cores. grid=(T/64, B*H), 128 threads (4 warps).
// Warp = 16 query rows. Q frags preloaded (scaled), K/V tf32 in smem,
// P round-trips through warp-private smem for the PV mma.
// ---------------------------------------------------------------------------
#define AL 68
#define ATTN_SMEM (3 * 64 * AL * 4)   // 52224 bytes

__global__ __launch_bounds__(128) void attn_tc() {
    extern __shared__ unsigned sma[];
    unsigned* Ks = sma;                // [64][AL] tf32
    unsigned* Vs = sma + 64 * AL;      // [64][AL] tf32
    unsigned* Ps = sma + 2 * 64 * AL;  // [64][AL]; doubles as fp32 Q staging
    float* Qf = (float*)Ps;

    const int tid = threadIdx.x, lane = tid & 31, w = tid >> 5;
    const int g = lane >> 2, tig = lane & 3;
    const int bh = blockIdx.y, i0 = blockIdx.x * 64;

    const float* Qg = g_qkv + ((size_t)bh * TT + i0) * DH;
    const float* Kg = g_qkv + (size_t)BB * HH * TT * DH + (size_t)bh * TT * DH;
    const float* Vg = Kg + (size_t)BB * HH * TT * DH;

    // Stage Q (fp32)
    #pragma unroll
    for (int rep = 0; rep < 8; rep++) {
        int ii = rep * 128 + tid;
        int row = ii >> 4, c4 = ii & 15;
        *(float4*)&Qf[row * AL + c4 * 4] =
            *(const float4*)(Qg + (size_t)row * DH + c4 * 4);
    }
    __syncthreads();

    // Preload Q A-fragments (scaled, tf32)
    unsigned qa[8][4];
    {
        const float* Qw = Qf + (w * 16) * AL;
        #pragma unroll
        for (int kit = 0; kit < 8; kit++) {
            qa[kit][0] = f2t(Qw[g * AL + kit * 8 + tig] * SCALE);
            qa[kit][1] = f2t(Qw[(g + 8) * AL + kit * 8 + tig] * SCALE);
            qa[kit][2] = f2t(Qw[g * AL + kit * 8 + tig + 4] * SCALE);
            qa[kit][3] = f2t(Qw[(g + 8) * AL + kit * 8 + tig + 4] * SCALE);
        }
    }
    unsigned* Pw = Ps + (w * 16) * AL;   // warp-private P region

    float oc[8][4];
    float mi0 = -1e30f, mi1 = -1e30f, li0 = 0.f, li1 = 0.f;
    #pragma unroll
    for (int nt = 0; nt < 8; nt++)
        #pragma unroll
        for (int i = 0; i < 4; i++) oc[nt][i] = 0.f;

    for (int j0 = 0; j0 < TT; j0 += 64) {
        __syncthreads();   // prior PV reads done before K/V overwrite (also fences P)
        #pragma unroll
        for (int rep = 0; rep < 8; rep++) {
            int ii = rep * 128 + tid;
            int row = ii >> 4, c4 = ii & 15;
            float4 kv = *(const float4*)(Kg + (size_t)(j0 + row) * DH + c4 * 4);
            *(uint4*)&Ks[row * AL + c4 * 4] =
                make_uint4(f2t(kv.x), f2t(kv.y), f2t(kv.z), f2t(kv.w));
            float4 vv = *(const float4*)(Vg + (size_t)(j0 + row) * DH + c4 * 4);
            *(uint4*)&Vs[row * AL + c4 * 4] =
                make_uint4(f2t(vv.x), f2t(vv.y), f2t(vv.z), f2t(vv.w));
        }
        __syncthreads();

        // S = (Q*SCALE) K^T : 16x64 per warp
        float sc[8][4];
        #pragma unroll
        for (int nt = 0; nt < 8; nt++)
            #pragma unroll
            for (int i = 0; i < 4; i++) sc[nt][i] = 0.f;
        #pragma unroll
        for (int kit = 0; kit < 8; kit++)
            #pragma unroll
            for (int nt = 0; nt < 8; nt++) {
                unsigned b0 = Ks[(nt * 8 + g) * AL + kit * 8 + tig];
                unsigned b1 = Ks[(nt * 8 + g) * AL + kit * 8 + tig + 4];
                mma8(sc[nt], qa[kit], b0, b1);
            }

        // Online softmax (rows g and g+8, shared across the 4 tig lanes)
        float ml0 = -1e30f, ml1 = -1e30f;
        #pragma unroll
        for (int nt = 0; nt < 8; nt++) {
            ml0 = fmaxf(ml0, fmaxf(sc[nt][0], sc[nt][1]));
            ml1 = fmaxf(ml1, fmaxf(sc[nt][2], sc[nt][3]));
        }
        ml0 = fmaxf(ml0, __shfl_xor_sync(0xffffffffu, ml0, 1));
        ml0 = fmaxf(ml0, __shfl_xor_sync(0xffffffffu, ml0, 2));
        ml1 = fmaxf(ml1, __shfl_xor_sync(0xffffffffu, ml1, 1));
        ml1 = fmaxf(ml1, __shfl_xor_sync(0xffffffffu, ml1, 2));
        float mn0 = fmaxf(mi0, ml0), mn1 = fmaxf(mi1, ml1);
        float al0 = __expf(mi0 - mn0), al1 = __expf(mi1 - mn1);
        mi0 = mn0; mi1 = mn1;

        float ls0 = 0.f, ls1 = 0.f;
        #pragma unroll
        for (int nt = 0; nt < 8; nt++) {
            float p0 = __expf(sc[nt][0] - mn0);
            float p1 = __expf(sc[nt][1] - mn0);
            float p2 = __expf(sc[nt][2] - mn1);
            float p3 = __expf(sc[nt][3] - mn1);
            ls0 += p0 + p1; ls1 += p2 + p3;
            *(uint2*)&Pw[g * AL + nt * 8 + 2 * tig]       = make_uint2(f2t(p0), f2t(p1));
            *(uint2*)&Pw[(g + 8) * AL + nt * 8 + 2 * tig] = make_uint2(f2t(p2), f2t(p3));
        }
        ls0 += __shfl_xor_sync(0xffffffffu, ls0, 1);
        ls0 += __shfl_xor_sync(0xffffffffu, ls0, 2);
        ls1 += __shfl_xor_sync(0xffffffffu, ls1, 1);
        ls1 += __shfl_xor_sync(0xffffffffu, ls1, 2);
        li0 = li0 * al0 + ls0;
        li1 = li1 * al1 + ls1;
        #pragma unroll
        for (int nt = 0; nt < 8; nt++) {
            oc[nt][0] *= al0; oc[nt][1] *= al0;
            oc[nt][2] *= al1; oc[nt][3] *= al1;
        }
        __syncwarp();

        // O += P V
        #pragma unroll
        for (int kit = 0; kit < 8; kit++) {
            unsigned pa[4];
            pa[0] = Pw[g * AL + kit * 8 + tig];
            pa[1] = Pw[(g + 8) * AL + kit * 8 + tig];
            pa[2] = Pw[g * AL + kit * 8 + tig + 4];
            pa[3] = Pw[(g + 8) * AL + kit * 8 + tig + 4];
            #pragma unroll
            for (int nt = 0; nt < 8; nt++) {
                unsigned b0 = Vs[(kit * 8 + tig) * AL + nt * 8 + g];
                unsigned b1 = Vs[(kit * 8 + tig + 4) * AL + nt * 8 + g];
                mma8(oc[nt], pa, b0, b1);
            }
        }
    }

    float inv0 = 1.f / li0, inv1 = 1.f / li1;
    int r0 = i0 + w * 16 + g, r1 = r0 + 8;
    #pragma unroll
    for (int nt = 0; nt < 8; nt++) {
        int d = nt * 8 + 2 * tig;
        *(float2*)&g_ao[((size_t)bh * TT + r0) * DH + d] =
            make_float2(oc[nt][0] * inv0, oc[nt][1] * inv0);
        *(float2*)&g_ao[((size_t)bh * TT + r1) * DH + d] =
            make_float2(oc[nt][2] * inv1, oc[nt][3] * inv1);
    }
}

// ---------------------------------------------------------------------------
extern "C" void kernel_launch(void* const* d_in, const int* in_sizes, int n_in,
                              void* d_out, int out_size) {
    const float* x    = (const float*)d_in[0];
    const float* wqkv = (const float*)d_in[1];
    const float* wout = (const float*)d_in[2];
    const float* bout = (const float*)d_in[3];
    float* y = (float*)d_out;

    cudaFuncSetAttribute(gemm_tc<0>, cudaFuncAttributeMaxDynamicSharedMemorySize, GEMM_SMEM);
    cudaFuncSetAttribute(gemm_tc<1>, cudaFuncAttributeMaxDynamicSharedMemorySize, GEMM_SMEM);
    cudaFuncSetAttribute(attn_tc, cudaFuncAttributeMaxDynamicSharedMemorySize, ATTN_SMEM);

    gemm_tc<0><<<dim3(24, 64), 256, GEMM_SMEM>>>(x, wqkv, nullptr, nullptr);
    attn_tc<<<dim3(TT / 64, BB * HH), 128, ATTN_SMEM>>>();
    gemm_tc<1><<<dim3(8, 64), 256, GEMM_SMEM>>>(nullptr, wout, bout, y);
}

// round 4
// speedup vs baseline: 4.2059x; 1.1865x over previous
#include <cuda_runtime.h>
#include <cstdint>

#define BB 4
#define TT 2048
#define FF 1024
#define HH 16
#define DH 64
#define SCALE 0.03125f   // 1024^-0.5

// Scratch (device globals: allocation-free, harness-legal). All tf32-bit floats.
__device__ float g_x [(size_t)BB * TT * FF];             // x, tf32-truncated
__device__ float g_wq[(size_t)3 * FF * FF];              // w_qkv permuted [kq,hq,d][f]
__device__ float g_wo[(size_t)FF * FF];                  // w_out
__device__ float g_qkv[(size_t)3 * BB * HH * TT * DH];   // [k][b][h][t][d] (q pre-scaled)
__device__ float g_ao[(size_t)BB * HH * TT * DH];        // [b][h][t][d]

__device__ __forceinline__ unsigned f2t(float f) {
    unsigned r; asm("cvt.rna.tf32.f32 %0, %1;" : "=r"(r) : "f"(f)); return r;
}
__device__ __forceinline__ float f2tf(float f) { return __uint_as_float(f2t(f)); }

__device__ __forceinline__ void mma8(float c[4], const unsigned a[4],
                                     unsigned b0, unsigned b1) {
    asm volatile(
        "mma.sync.aligned.m16n8k8.row.col.f32.tf32.tf32.f32 "
        "{%0,%1,%2,%3},{%4,%5,%6,%7},{%8,%9},{%0,%1,%2,%3};"
        : "+f"(c[0]), "+f"(c[1]), "+f"(c[2]), "+f"(c[3])
        : "r"(a[0]), "r"(a[1]), "r"(a[2]), "r"(a[3]), "r"(b0), "r"(b1));
}
__device__ __forceinline__ void cpa16(uint32_t s, const void* g) {
    asm volatile("cp.async.cg.shared.global [%0], [%1], 16;" :: "r"(s), "l"(g));
}
__device__ __forceinline__ void cpa_commit() {
    asm volatile("cp.async.commit_group;");
}
template<int N> __device__ __forceinline__ void cpa_wait() {
    asm volatile("cp.async.wait_group %0;" :: "n"(N));
}

// ---------------------------------------------------------------------------
// Pre-pass: convert x, w_out to tf32 bits; permute+convert w_qkv.
// g_wq row n (n = kq*1024 + hq*64 + d) = w_qkv row (d*48 + kq*16 + hq).
// ---------------------------------------------------------------------------
#define XT4 ((size_t)BB * TT * FF / 4)       // 2097152
#define WQ4 ((size_t)3 * FF * FF / 4)        // 786432
#define WO4 ((size_t)FF * FF / 4)            // 262144

__global__ __launch_bounds__(256) void conv_kernel(const float* __restrict__ x,
                                                   const float* __restrict__ wq,
                                                   const float* __restrict__ wo) {
    size_t i = (size_t)blockIdx.x * 256 + threadIdx.x;
    const float4* src; float* dst;
    if (i < XT4) {
        src = (const float4*)x + i; dst = g_x + i * 4;
    } else if (i < XT4 + WQ4) {
        size_t j = i - XT4;
        int n = (int)(j >> 8), c4 = (int)(j & 255);
        int kq = n >> 10, hq = (n >> 6) & 15, d = n & 63;
        src = (const float4*)(wq + (size_t)(d * 48 + kq * 16 + hq) * FF) + c4;
        dst = g_wq + (size_t)n * FF + c4 * 4;
    } else if (i < XT4 + WQ4 + WO4) {
        size_t j = i - XT4 - WQ4;
        src = (const float4*)wo + j; dst = g_wo + j * 4;
    } else return;
    float4 v = *src;
    *(float4*)dst = make_float4(f2tf(v.x), f2tf(v.y), f2tf(v.z), f2tf(v.w));
}

// ---------------------------------------------------------------------------
// Tensor-core GEMM, 256x128 CTA tile, k-tile 32, 8 warps (4m x 2n), 64x64/warp.
// cp.async double-buffered. Operands already tf32 bits in gmem (no cvt here).
// MODE 0: A=g_x, B=g_wq, C -> g_qkv (tf32 bits, q rows scaled)
// MODE 1: A=g_ao (head gather), B=g_wo, C -> y + bias (fp32)
// ---------------------------------------------------------------------------
#define GLD 36
#define GEMM_SMEM ((2 * 256 * GLD + 2 * 128 * GLD) * 4)   // 110592 B

template<int MODE>
__global__ __launch_bounds__(256) void gemm_tc(const float* __restrict__ bias,
                                               float* __restrict__ out) {
    extern __shared__ unsigned smg[];
    unsigned* As = smg;                   // [2][256][GLD]
    unsigned* Bs = smg + 2 * 256 * GLD;   // [2][128][GLD]

    const int tid = threadIdx.x;
    const int lane = tid & 31, w = tid >> 5;
    const int g = lane >> 2, tig = lane & 3;
    const int wm = (w & 3) * 64, wn = (w >> 2) * 64;
    const int m0 = blockIdx.y * 256, n0 = blockIdx.x * 128;
    const int lrow = tid >> 3;           // 0..31
    const int kc = (tid & 7) * 4;

    const uint32_t sbase = (uint32_t)__cvta_generic_to_shared(smg);

    float acc[4][8][4];
    #pragma unroll
    for (int mt = 0; mt < 4; mt++)
        #pragma unroll
        for (int nt = 0; nt < 8; nt++)
            #pragma unroll
            for (int i = 0; i < 4; i++) acc[mt][nt][i] = 0.f;

    auto issue = [&](int stage, int k0) {
        // A: 256 rows, 8 per thread
        #pragma unroll
        for (int r = 0; r < 8; r++) {
            int row = lrow + r * 32;
            const float* src;
            if (MODE == 0) {
                src = g_x + (size_t)(m0 + row) * FF + k0 + kc;
            } else {
                int m = m0 + row; int b = m >> 11, t = m & 2047;
                int kk = k0 + kc; int h = kk >> 6, dd = kk & 63;
                src = g_ao + (((size_t)b * HH + h) * TT + t) * DH + dd;
            }
            cpa16(sbase + (uint32_t)(stage * 256 * GLD + row * GLD + kc) * 4, src);
        }
        // B: 128 rows, 4 per thread
        #pragma unroll
        for (int r = 0; r < 4; r++) {
            int row = lrow + r * 32;
            const float* src = (MODE == 0 ? g_wq : g_wo) +
                               (size_t)(n0 + row) * FF + k0 + kc;
            cpa16(sbase + (uint32_t)(2 * 256 * GLD + stage * 128 * GLD + row * GLD + kc) * 4, src);
        }
        cpa_commit();
    };

    issue(0, 0);
    const int NK = FF / 32;
    #pragma unroll 1
    for (int kt = 0; kt < NK; kt++) {
        cpa_wait<0>();
        __syncthreads();
        if (kt + 1 < NK) issue((kt + 1) & 1, (kt + 1) * 32);

        const unsigned* Ab = As + (kt & 1) * 256 * GLD;
        const unsigned* Bb = Bs + (kt & 1) * 128 * GLD;
        #pragma unroll
        for (int kit = 0; kit < 4; kit++) {
            unsigned a[4][4], b[8][2];
            #pragma unroll
            for (int mt = 0; mt < 4; mt++) {
                int mrow = wm + mt * 16 + g;
                a[mt][0] = Ab[mrow * GLD + kit * 8 + tig];
                a[mt][1] = Ab[(mrow + 8) * GLD + kit * 8 + tig];
                a[mt][2] = Ab[mrow * GLD + kit * 8 + tig + 4];
                a[mt][3] = Ab[(mrow + 8) * GLD + kit * 8 + tig + 4];
            }
            #pragma unroll
            for (int nt = 0; nt < 8; nt++) {
                int nrow = wn + nt * 8 + g;
                b[nt][0] = Bb[nrow * GLD + kit * 8 + tig];
                b[nt][1] = Bb[nrow * GLD + kit * 8 + tig + 4];
            }
            #pragma unroll
            for (int mt = 0; mt < 4; mt++)
                #pragma unroll
                for (int nt = 0; nt < 8; nt++)
                    mma8(acc[mt][nt], a[mt], b[nt][0], b[nt][1]);
        }
    }

    #pragma unroll
    for (int mt = 0; mt < 4; mt++)
        #pragma unroll
        for (int nt = 0; nt < 8; nt++) {
            int n = n0 + wn + nt * 8 + 2 * tig;
            #pragma unroll
            for (int half = 0; half < 2; half++) {
                int m = m0 + wm + mt * 16 + g + half * 8;
                float c0 = acc[mt][nt][half * 2 + 0];
                float c1 = acc[mt][nt][half * 2 + 1];
                if (MODE == 0) {
                    int b = m >> 11, t = m & 2047;
                    int kq = n >> 10, hq = (n >> 6) & 15, d = n & 63;
                    if (kq == 0) { c0 *= SCALE; c1 *= SCALE; }
                    *(float2*)&g_qkv[((((size_t)kq * BB + b) * HH + hq) * TT + t) * DH + d] =
                        make_float2(f2tf(c0), f2tf(c1));
                } else {
                    float2 bv = *(const float2*)&bias[n];
                    *(float2*)&out[(size_t)m * FF + n] =
                        make_float2(c0 + bv.x, c1 + bv.y);
                }
            }
        }
}

// ---------------------------------------------------------------------------
// Flash attention. grid=(T/128, B*H), 256 threads (8 warps), warp = 16 q-rows.
// K/V double-buffered via cp.async (already tf32 bits, Q pre-scaled).
// K pad 68 (row-frag conflict-free), V pad 72 (col-frag conflict-free).
// ---------------------------------------------------------------------------
#define KL 68
#define VL 72
#define PL 68
#define ATTN_SMEM ((2 * 64 * KL + 2 * 64 * VL + 128 * PL) * 4)   // 106496 B

__global__ __launch_bounds__(256) void attn_tc() {
    extern __shared__ unsigned sma[];
    unsigned* Ks = sma;                       // [2][64][KL]
    unsigned* Vs = sma + 2 * 64 * KL;         // [2][64][VL]
    unsigned* Ps = sma + 2 * 64 * KL + 2 * 64 * VL;  // [128][PL]

    const int tid = threadIdx.x, lane = tid & 31, w = tid >> 5;
    const int g = lane >> 2, tig = lane & 3;
    const int bh = blockIdx.y, i0 = blockIdx.x * 128;

    const float* Qg = g_qkv + ((size_t)bh * TT + i0) * DH;
    const float* Kg = g_qkv + (size_t)BB * HH * TT * DH + (size_t)bh * TT * DH;
    const float* Vg = Kg + (size_t)BB * HH * TT * DH;

    const uint32_t sbase = (uint32_t)__cvta_generic_to_shared(sma);
    const uint32_t ksoff = 0, vsoff = 2 * 64 * KL;

    // Stage Q (raw tf32 bits) into Ps, then preload A-fragments.
    #pragma unroll
    for (int rep = 0; rep < 8; rep++) {
        int ii = rep * 256 + tid;
        int row = ii >> 4, c4 = ii & 15;
        *(uint4*)&Ps[row * PL + c4 * 4] =
            *(const uint4*)(Qg + (size_t)row * DH + c4 * 4);
    }
    __syncthreads();
    unsigned qa[8][4];
    {
        const unsigned* Qw = Ps + (w * 16) * PL;
        #pragma unroll
        for (int kit = 0; kit < 8; kit++) {
            qa[kit][0] = Qw[g * PL + kit * 8 + tig];
            qa[kit][1] = Qw[(g + 8) * PL + kit * 8 + tig];
            qa[kit][2] = Qw[g * PL + kit * 8 + tig + 4];
            qa[kit][3] = Qw[(g + 8) * PL + kit * 8 + tig + 4];
        }
    }
    __syncthreads();
    unsigned* Pw = Ps + (w * 16) * PL;   // warp-private P region

    auto issue = [&](int stage, int j0) {
        #pragma unroll
        for (int r = 0; r < 4; r++) {
            int ii = r * 256 + tid;
            int row = ii >> 4, c4 = (ii & 15) * 4;
            cpa16(sbase + (uint32_t)(ksoff + stage * 64 * KL + row * KL + c4) * 4,
                  Kg + (size_t)(j0 + row) * DH + c4);
            cpa16(sbase + (uint32_t)(vsoff + stage * 64 * VL + row * VL + c4) * 4,
                  Vg + (size_t)(j0 + row) * DH + c4);
        }
        cpa_commit();
    };

    float oc[8][4];
    float mi0 = -1e30f, mi1 = -1e30f, li0 = 0.f, li1 = 0.f;
    #pragma unroll
    for (int nt = 0; nt < 8; nt++)
        #pragma unroll
        for (int i = 0; i < 4; i++) oc[nt][i] = 0.f;

    issue(0, 0);
    const int NJ = TT / 64;
    #pragma unroll 1
    for (int jt = 0; jt < NJ; jt++) {
        cpa_wait<0>();
        __syncthreads();
        if (jt + 1 < NJ) issue((jt + 1) & 1, (jt + 1) * 64);

        const unsigned* Kb = Ks + (jt & 1) * 64 * KL;
        const unsigned* Vb = Vs + (jt & 1) * 64 * VL;

        // S = Q K^T : 16x64 per warp
        float sc[8][4];
        #pragma unroll
        for (int nt = 0; nt < 8; nt++)
            #pragma unroll
            for (int i = 0; i < 4; i++) sc[nt][i] = 0.f;
        #pragma unroll
        for (int kit = 0; kit < 8; kit++)
            #pragma unroll
            for (int nt = 0; nt < 8; nt++) {
                unsigned b0 = Kb[(nt * 8 + g) * KL + kit * 8 + tig];
                unsigned b1 = Kb[(nt * 8 + g) * KL + kit * 8 + tig + 4];
                mma8(sc[nt], qa[kit], b0, b1);
            }

        // Online softmax (rows g, g+8 shared across 4 tig lanes)
        float ml0 = -1e30f, ml1 = -1e30f;
        #pragma unroll
        for (int nt = 0; nt < 8; nt++) {
            ml0 = fmaxf(ml0, fmaxf(sc[nt][0], sc[nt][1]));
            ml1 = fmaxf(ml1, fmaxf(sc[nt][2], sc[nt][3]));
        }
        ml0 = fmaxf(ml0, __shfl_xor_sync(0xffffffffu, ml0, 1));
        ml0 = fmaxf(ml0, __shfl_xor_sync(0xffffffffu, ml0, 2));
        ml1 = fmaxf(ml1, __shfl_xor_sync(0xffffffffu, ml1, 1));
        ml1 = fmaxf(ml1, __shfl_xor_sync(0xffffffffu, ml1, 2));
        float mn0 = fmaxf(mi0, ml0), mn1 = fmaxf(mi1, ml1);
        float al0 = __expf(mi0 - mn0), al1 = __expf(mi1 - mn1);
        mi0 = mn0; mi1 = mn1;

        float ls0 = 0.f, ls1 = 0.f;
        #pragma unroll
        for (int nt = 0; nt < 8; nt++) {
            float p0 = __expf(sc[nt][0] - mn0);
            float p1 = __expf(sc[nt][1] - mn0);
            float p2 = __expf(sc[nt][2] - mn1);
            float p3 = __expf(sc[nt][3] - mn1);
            ls0 += p0 + p1; ls1 += p2 + p3;
            *(uint2*)&Pw[g * PL + nt * 8 + 2 * tig]       = make_uint2(f2t(p0), f2t(p1));
            *(uint2*)&Pw[(g + 8) * PL + nt * 8 + 2 * tig] = make_uint2(f2t(p2), f2t(p3));
        }
        ls0 += __shfl_xor_sync(0xffffffffu, ls0, 1);
        ls0 += __shfl_xor_sync(0xffffffffu, ls0, 2);
        ls1 += __shfl_xor_sync(0xffffffffu, ls1, 1);
        ls1 += __shfl_xor_sync(0xffffffffu, ls1, 2);
        li0 = li0 * al0 + ls0;
        li1 = li1 * al1 + ls1;
        #pragma unroll
        for (int nt = 0; nt < 8; nt++) {
            oc[nt][0] *= al0; oc[nt][1] *= al0;
            oc[nt][2] *= al1; oc[nt][3] *= al1;
        }
        __syncwarp();

        // O += P V
        #pragma unroll
        for (int kit = 0; kit < 8; kit++) {
            unsigned pa[4];
            pa[0] = Pw[g * PL + kit * 8 + tig];
            pa[1] = Pw[(g + 8) * PL + kit * 8 + tig];
            pa[2] = Pw[g * PL + kit * 8 + tig + 4];
            pa[3] = Pw[(g + 8) * PL + kit * 8 + tig + 4];
            #pragma unroll
            for (int nt = 0; nt < 8; nt++) {
                unsigned b0 = Vb[(kit * 8 + tig) * VL + nt * 8 + g];
                unsigned b1 = Vb[(kit * 8 + tig + 4) * VL + nt * 8 + g];
                mma8(oc[nt], pa, b0, b1);
            }
        }
        __syncwarp();   // P reads done before next iteration overwrites Pw
    }

    float inv0 = 1.f / li0, inv1 = 1.f / li1;
    int r0 = i0 + w * 16 + g, r1 = r0 + 8;
    #pragma unroll
    for (int nt = 0; nt < 8; nt++) {
        int d = nt * 8 + 2 * tig;
        *(float2*)&g_ao[((size_t)bh * TT + r0) * DH + d] =
            make_float2(f2tf(oc[nt][0] * inv0), f2tf(oc[nt][1] * inv0));
        *(float2*)&g_ao[((size_t)bh * TT + r1) * DH + d] =
            make_float2(f2tf(oc[nt][2] * inv1), f2tf(oc[nt][3] * inv1));
    }
}

// ---------------------------------------------------------------------------
extern "C" void kernel_launch(void* const* d_in, const int* in_sizes, int n_in,
                              void* d_out, int out_size) {
    const float* x    = (const float*)d_in[0];
    const float* wqkv = (const float*)d_in[1];
    const float* wout = (const float*)d_in[2];
    const float* bout = (const float*)d_in[3];
    float* y = (float*)d_out;

    cudaFuncSetAttribute(gemm_tc<0>, cudaFuncAttributeMaxDynamicSharedMemorySize, GEMM_SMEM);
    cudaFuncSetAttribute(gemm_tc<1>, cudaFuncAttributeMaxDynamicSharedMemorySize, GEMM_SMEM);
    cudaFuncSetAttribute(attn_tc, cudaFuncAttributeMaxDynamicSharedMemorySize, ATTN_SMEM);

    size_t total4 = XT4 + WQ4 + WO4;
    conv_kernel<<<(unsigned)((total4 + 255) / 256), 256>>>(x, wqkv, wout);
    gemm_tc<0><<<dim3(24, 32), 256, GEMM_SMEM>>>(nullptr, nullptr);
    attn_tc<<<dim3(TT / 128, BB * HH), 256, ATTN_SMEM>>>();
    gemm_tc<1><<<dim3(8, 32), 256, GEMM_SMEM>>>(bout, y);
}